// round 16
// baseline (speedup 1.0000x reference)
#include <cuda_runtime.h>
#include <cuda_bf16.h>

#define FEATS 64
#define MAX_NODES 100000
#define MAX_EDGES 1000000
#define SCAN_BLK 1024

// ---- scratch (__device__ globals; no allocs allowed) ----
__device__ float g_sum[(size_t)MAX_NODES * FEATS];
__device__ float g_deg[MAX_NODES];
__device__ int   g_count[MAX_NODES];
__device__ int   g_incl[MAX_NODES];
__device__ int   g_start[MAX_NODES];
__device__ int   g_cursor[MAX_NODES];
__device__ int   g_blocksums[128];
__device__ int   g_edge_src[MAX_EDGES];

// ---------------------------------------------------------------------------
// packed f32x2 helpers (sm_103a)
// ---------------------------------------------------------------------------
__device__ __forceinline__ unsigned long long fma2(unsigned long long a,
                                                   unsigned long long b,
                                                   unsigned long long c) {
    unsigned long long d;
    asm("fma.rn.f32x2 %0, %1, %2, %3;" : "=l"(d) : "l"(a), "l"(b), "l"(c));
    return d;
}
__device__ __forceinline__ unsigned long long pack2(float v) {
    unsigned long long d;
    asm("mov.b64 %0, {%1, %1};" : "=l"(d) : "f"(v));
    return d;
}

// ---------------------------------------------------------------------------
// 1) zero int degree counters
// ---------------------------------------------------------------------------
__global__ void zero_counts(int n_nodes) {
    int i = blockIdx.x * blockDim.x + threadIdx.x;
    if (i < n_nodes) g_count[i] = 0;
}

// ---------------------------------------------------------------------------
// 2) histogram of dst (scalar — proven fastest)
// ---------------------------------------------------------------------------
__global__ void hist_kernel(const int* __restrict__ dst, int n_edges) {
    int e = blockIdx.x * blockDim.x + threadIdx.x;
    if (e < n_edges) atomicAdd(&g_count[dst[e]], 1);
}

// ---------------------------------------------------------------------------
// 3a) per-block (1024) inclusive scan via warp shuffles
// ---------------------------------------------------------------------------
__global__ __launch_bounds__(SCAN_BLK) void scan1(int n_nodes) {
    __shared__ int wsum[32];
    int tid  = threadIdx.x;
    int lane = tid & 31, wid = tid >> 5;
    int i = blockIdx.x * SCAN_BLK + tid;
    int v = (i < n_nodes) ? g_count[i] : 0;
    int s = v;
    #pragma unroll
    for (int off = 1; off < 32; off <<= 1) {
        int t = __shfl_up_sync(0xffffffffu, s, off);
        if (lane >= off) s += t;
    }
    if (lane == 31) wsum[wid] = s;
    __syncthreads();
    if (wid == 0) {
        int w = wsum[lane];
        #pragma unroll
        for (int off = 1; off < 32; off <<= 1) {
            int t = __shfl_up_sync(0xffffffffu, w, off);
            if (lane >= off) w += t;
        }
        wsum[lane] = w;
    }
    __syncthreads();
    int incl = s + (wid > 0 ? wsum[wid - 1] : 0);
    if (i < n_nodes) g_incl[i] = incl;
    if (tid == SCAN_BLK - 1) g_blocksums[blockIdx.x] = incl;
}

// ---------------------------------------------------------------------------
// 3b) finalize: redundant scan of block sums + row starts + cursors + degree
// ---------------------------------------------------------------------------
__global__ __launch_bounds__(256) void scan3(int n_nodes, int nb) {
    __shared__ int sbs[128];
    int t = threadIdx.x;
    if (t < 128) sbs[t] = (t < nb) ? g_blocksums[t] : 0;
    __syncthreads();
    #pragma unroll
    for (int off = 1; off < 128; off <<= 1) {
        int v = 0;
        if (t < 128 && t >= off) v = sbs[t - off];
        __syncthreads();
        if (t < 128) sbs[t] += v;
        __syncthreads();
    }
    int i = blockIdx.x * 256 + t;
    if (i < n_nodes) {
        int chunk = i / SCAN_BLK;
        int pre = (chunk == 0) ? 0 : sbs[chunk - 1];
        int cnt = g_count[i];
        int st = g_incl[i] - cnt + pre;
        g_start[i]  = st;
        g_cursor[i] = st;
        g_deg[i]    = (float)cnt;
    }
}

// ---------------------------------------------------------------------------
// 4) reorder (scalar — proven fastest)
// ---------------------------------------------------------------------------
__global__ void reorder_kernel(const int* __restrict__ src,
                               const int* __restrict__ dst, int n_edges) {
    int e = blockIdx.x * blockDim.x + threadIdx.x;
    if (e < n_edges) {
        int p = atomicAdd(&g_cursor[dst[e]], 1);
        g_edge_src[p] = src[e];
    }
}

// ---------------------------------------------------------------------------
// 5) MERGED gather + self-GEMM (single launch, single stream):
//    blocks [0, nb_self)        : out_raw = x @ Ws (128-row tiles)
//    blocks [nb_self, nb_total) : CSR gather into g_sum (proven code)
// ---------------------------------------------------------------------------
#define SAT_STRIDE 132
#define SAT_BYTES  (64 * SAT_STRIDE * 4)                  // 33792
#define SELF_SMEM  (SAT_BYTES + 16384)                    // 50176
#define FINAL_SMEM (SAT_BYTES + 16384 + 256 + 512)        // 50944

__global__ __launch_bounds__(256) void gather_self_kernel(
        const float* __restrict__ x,
        const float* __restrict__ Ws,
        float* __restrict__ out,
        int n_rows, int nb_self) {
    if ((int)blockIdx.x < nb_self) {
        // ---------------- self-GEMM path ----------------
        extern __shared__ char smem[];
        float*  sAT = reinterpret_cast<float*>(smem);                 // [64][132]
        float4* sW  = reinterpret_cast<float4*>(smem + SAT_BYTES);    // [64][16]

        int tid  = threadIdx.x;
        int row0 = blockIdx.x * 128;

        {
            const float4* gW = reinterpret_cast<const float4*>(Ws);
            #pragma unroll
            for (int i = 0; i < 4; i++) {
                int idx = tid + 256 * i;
                sW[idx] = __ldg(&gW[idx]);
            }
        }
        {
            const float4* gx = reinterpret_cast<const float4*>(x);
            #pragma unroll
            for (int i = 0; i < 8; i++) {
                int idx = tid + 256 * i;
                int r = (idx & 7) | ((idx >> 7) << 3);
                int c = ((idx >> 3) & 3) | (((idx >> 5) & 3) << 2);
                int grow = row0 + r;
                float4 v = make_float4(0.f, 0.f, 0.f, 0.f);
                if (grow < n_rows) v = __ldg(&gx[(size_t)grow * 16 + c]);
                sAT[(4 * c + 0) * SAT_STRIDE + r] = v.x;
                sAT[(4 * c + 1) * SAT_STRIDE + r] = v.y;
                sAT[(4 * c + 2) * SAT_STRIDE + r] = v.z;
                sAT[(4 * c + 3) * SAT_STRIDE + r] = v.w;
            }
        }
        __syncthreads();

        int ty = tid >> 4, tx = tid & 15;
        int rbase = ty * 8;

        unsigned long long acc[4][4];
        #pragma unroll
        for (int p = 0; p < 4; p++)
            #pragma unroll
            for (int c = 0; c < 4; c++) acc[p][c] = 0ull;

        #pragma unroll 8
        for (int k = 0; k < FEATS; k++) {
            const float* ap = &sAT[k * SAT_STRIDE + rbase];
            ulonglong2 A01 = *reinterpret_cast<const ulonglong2*>(ap);
            ulonglong2 A23 = *reinterpret_cast<const ulonglong2*>(ap + 4);
            float4 w = sW[k * 16 + tx];
            unsigned long long w0 = pack2(w.x), w1 = pack2(w.y),
                               w2 = pack2(w.z), w3 = pack2(w.w);
            acc[0][0]=fma2(A01.x,w0,acc[0][0]); acc[0][1]=fma2(A01.x,w1,acc[0][1]);
            acc[0][2]=fma2(A01.x,w2,acc[0][2]); acc[0][3]=fma2(A01.x,w3,acc[0][3]);
            acc[1][0]=fma2(A01.y,w0,acc[1][0]); acc[1][1]=fma2(A01.y,w1,acc[1][1]);
            acc[1][2]=fma2(A01.y,w2,acc[1][2]); acc[1][3]=fma2(A01.y,w3,acc[1][3]);
            acc[2][0]=fma2(A23.x,w0,acc[2][0]); acc[2][1]=fma2(A23.x,w1,acc[2][1]);
            acc[2][2]=fma2(A23.x,w2,acc[2][2]); acc[2][3]=fma2(A23.x,w3,acc[2][3]);
            acc[3][0]=fma2(A23.y,w0,acc[3][0]); acc[3][1]=fma2(A23.y,w1,acc[3][1]);
            acc[3][2]=fma2(A23.y,w2,acc[3][2]); acc[3][3]=fma2(A23.y,w3,acc[3][3]);
        }

        float4* out4 = reinterpret_cast<float4*>(out);
        #pragma unroll
        for (int p = 0; p < 4; p++) {
            float2 c0 = *reinterpret_cast<float2*>(&acc[p][0]);
            float2 c1 = *reinterpret_cast<float2*>(&acc[p][1]);
            float2 c2 = *reinterpret_cast<float2*>(&acc[p][2]);
            float2 c3 = *reinterpret_cast<float2*>(&acc[p][3]);
            int row_lo = row0 + rbase + 2 * p;
            if (row_lo < n_rows)
                out4[(size_t)row_lo * 16 + tx] = make_float4(c0.x, c1.x, c2.x, c3.x);
            int row_hi = row_lo + 1;
            if (row_hi < n_rows)
                out4[(size_t)row_hi * 16 + tx] = make_float4(c0.y, c1.y, c2.y, c3.y);
        }
    } else {
        // ---------------- gather path (proven) ----------------
        int bid  = (int)blockIdx.x - nb_self;
        int grp  = (bid * 256 + (int)threadIdx.x) >> 4;
        int lane = threadIdx.x & 15;
        if (grp >= n_rows) return;
        int s0  = g_start[grp];
        int deg = g_count[grp];
        const float4* x4 = reinterpret_cast<const float4*>(x);
        float4 acc = make_float4(0.f, 0.f, 0.f, 0.f);

        int j = 0;
        for (; j + 4 <= deg; j += 4) {
            int i0 = __ldg(&g_edge_src[s0 + j + 0]);
            int i1 = __ldg(&g_edge_src[s0 + j + 1]);
            int i2 = __ldg(&g_edge_src[s0 + j + 2]);
            int i3 = __ldg(&g_edge_src[s0 + j + 3]);
            float4 v0 = __ldg(&x4[(size_t)i0 * 16 + lane]);
            float4 v1 = __ldg(&x4[(size_t)i1 * 16 + lane]);
            float4 v2 = __ldg(&x4[(size_t)i2 * 16 + lane]);
            float4 v3 = __ldg(&x4[(size_t)i3 * 16 + lane]);
            acc.x += v0.x + v1.x + v2.x + v3.x;
            acc.y += v0.y + v1.y + v2.y + v3.y;
            acc.z += v0.z + v1.z + v2.z + v3.z;
            acc.w += v0.w + v1.w + v2.w + v3.w;
        }
        for (; j < deg; j++) {
            int i0 = __ldg(&g_edge_src[s0 + j]);
            float4 v = __ldg(&x4[(size_t)i0 * 16 + lane]);
            acc.x += v.x;  acc.y += v.y;  acc.z += v.z;  acc.w += v.w;
        }
        reinterpret_cast<float4*>(g_sum)[(size_t)grp * 16 + lane] = acc;
    }
}

// ---------------------------------------------------------------------------
// 6) FINAL: out = relu(self(out) + (g_sum/max(deg,1))@Wn + b)
//    FIX vs R13/R15: __syncthreads() between sinv write and sinv read.
// ---------------------------------------------------------------------------
__global__ __launch_bounds__(256) void final_kernel(const float* __restrict__ Wn,
                                                    const float* __restrict__ b,
                                                    float* __restrict__ out,
                                                    int n_rows) {
    extern __shared__ char smem[];
    float*  sAT = reinterpret_cast<float*>(smem);                       // [64][132]
    float4* sW  = reinterpret_cast<float4*>(smem + SAT_BYTES);          // [64][16]
    float*  sb   = reinterpret_cast<float*>(smem + SAT_BYTES + 16384);  // [64]
    float*  sinv = sb + 64;                                             // [128]

    int tid  = threadIdx.x;
    int row0 = blockIdx.x * 128;

    {
        const float4* gW = reinterpret_cast<const float4*>(Wn);
        #pragma unroll
        for (int i = 0; i < 4; i++) {
            int idx = tid + 256 * i;
            sW[idx] = __ldg(&gW[idx]);
        }
        if (tid < FEATS) sb[tid] = b[tid];
        if (tid < 128) {
            int r = row0 + tid;
            float dg = (r < n_rows) ? g_deg[r] : 1.0f;
            sinv[tid] = 1.0f / fmaxf(dg, 1.0f);
        }
    }
    __syncthreads();    // *** the fix: sinv must be visible before staging ***

    {
        const float4* gs = reinterpret_cast<const float4*>(g_sum);
        #pragma unroll
        for (int i = 0; i < 8; i++) {
            int idx = tid + 256 * i;
            int r = (idx & 7) | ((idx >> 7) << 3);
            int c = ((idx >> 3) & 3) | (((idx >> 5) & 3) << 2);
            int grow = row0 + r;
            float4 v = make_float4(0.f, 0.f, 0.f, 0.f);
            if (grow < n_rows) {
                v = gs[(size_t)grow * 16 + c];
                float inv = sinv[r];
                v.x *= inv; v.y *= inv; v.z *= inv; v.w *= inv;
            }
            sAT[(4 * c + 0) * SAT_STRIDE + r] = v.x;
            sAT[(4 * c + 1) * SAT_STRIDE + r] = v.y;
            sAT[(4 * c + 2) * SAT_STRIDE + r] = v.z;
            sAT[(4 * c + 3) * SAT_STRIDE + r] = v.w;
        }
    }
    __syncthreads();

    int ty = tid >> 4, tx = tid & 15;
    int rbase = ty * 8;

    unsigned long long acc[4][4];
    #pragma unroll
    for (int p = 0; p < 4; p++)
        #pragma unroll
        for (int c = 0; c < 4; c++) acc[p][c] = 0ull;

    #pragma unroll 8
    for (int k = 0; k < FEATS; k++) {
        const float* ap = &sAT[k * SAT_STRIDE + rbase];
        ulonglong2 A01 = *reinterpret_cast<const ulonglong2*>(ap);
        ulonglong2 A23 = *reinterpret_cast<const ulonglong2*>(ap + 4);
        float4 w = sW[k * 16 + tx];
        unsigned long long w0 = pack2(w.x), w1 = pack2(w.y),
                           w2 = pack2(w.z), w3 = pack2(w.w);
        acc[0][0]=fma2(A01.x,w0,acc[0][0]); acc[0][1]=fma2(A01.x,w1,acc[0][1]);
        acc[0][2]=fma2(A01.x,w2,acc[0][2]); acc[0][3]=fma2(A01.x,w3,acc[0][3]);
        acc[1][0]=fma2(A01.y,w0,acc[1][0]); acc[1][1]=fma2(A01.y,w1,acc[1][1]);
        acc[1][2]=fma2(A01.y,w2,acc[1][2]); acc[1][3]=fma2(A01.y,w3,acc[1][3]);
        acc[2][0]=fma2(A23.x,w0,acc[2][0]); acc[2][1]=fma2(A23.x,w1,acc[2][1]);
        acc[2][2]=fma2(A23.x,w2,acc[2][2]); acc[2][3]=fma2(A23.x,w3,acc[2][3]);
        acc[3][0]=fma2(A23.y,w0,acc[3][0]); acc[3][1]=fma2(A23.y,w1,acc[3][1]);
        acc[3][2]=fma2(A23.y,w2,acc[3][2]); acc[3][3]=fma2(A23.y,w3,acc[3][3]);
    }

    float4 bb = reinterpret_cast<const float4*>(sb)[tx];
    float4* out4 = reinterpret_cast<float4*>(out);
    #pragma unroll
    for (int p = 0; p < 4; p++) {
        float2 c0 = *reinterpret_cast<float2*>(&acc[p][0]);
        float2 c1 = *reinterpret_cast<float2*>(&acc[p][1]);
        float2 c2 = *reinterpret_cast<float2*>(&acc[p][2]);
        float2 c3 = *reinterpret_cast<float2*>(&acc[p][3]);
        int row_lo = row0 + rbase + 2 * p;
        if (row_lo < n_rows) {
            float4 s = out4[(size_t)row_lo * 16 + tx];
            float4 o;
            o.x = fmaxf(s.x + c0.x + bb.x, 0.f);
            o.y = fmaxf(s.y + c1.x + bb.y, 0.f);
            o.z = fmaxf(s.z + c2.x + bb.z, 0.f);
            o.w = fmaxf(s.w + c3.x + bb.w, 0.f);
            out4[(size_t)row_lo * 16 + tx] = o;
        }
        int row_hi = row_lo + 1;
        if (row_hi < n_rows) {
            float4 s = out4[(size_t)row_hi * 16 + tx];
            float4 o;
            o.x = fmaxf(s.x + c0.y + bb.x, 0.f);
            o.y = fmaxf(s.y + c1.y + bb.y, 0.f);
            o.z = fmaxf(s.z + c2.y + bb.z, 0.f);
            o.w = fmaxf(s.w + c3.y + bb.w, 0.f);
            out4[(size_t)row_hi * 16 + tx] = o;
        }
    }
}

// ---------------------------------------------------------------------------
// Launch (single stream; overlap via merged launch)
// ---------------------------------------------------------------------------
extern "C" void kernel_launch(void* const* d_in, const int* in_sizes, int n_in,
                              void* d_out, int out_size) {
    const float* x   = (const float*)d_in[0];
    const float* Ws  = (const float*)d_in[1];
    const float* Wn  = (const float*)d_in[2];
    const float* b   = (const float*)d_in[3];
    const int*   src = (const int*)d_in[4];
    const int*   dst = (const int*)d_in[5];
    float* out = (float*)d_out;

    int n_edges = in_sizes[4];
    if (n_edges > MAX_EDGES) n_edges = MAX_EDGES;
    int n_rows = out_size / FEATS;
    if (n_rows > MAX_NODES) n_rows = MAX_NODES;

    int nb_nodes = (n_rows + 255) / 256;
    int nb_edges = (n_edges + 255) / 256;
    int nb_scan  = (n_rows + SCAN_BLK - 1) / SCAN_BLK;
    int nb_self  = (n_rows + 127) / 128;
    int nb_gath  = (int)(((long long)n_rows * 16 + 255) / 256);

    static int once = 0;
    if (!once) {
        cudaFuncSetAttribute(gather_self_kernel,
                             cudaFuncAttributeMaxDynamicSharedMemorySize,
                             SELF_SMEM);
        cudaFuncSetAttribute(final_kernel,
                             cudaFuncAttributeMaxDynamicSharedMemorySize,
                             FINAL_SMEM);
        once = 1;
    }

    zero_counts<<<nb_nodes, 256>>>(n_rows);
    hist_kernel<<<nb_edges, 256>>>(dst, n_edges);
    scan1<<<nb_scan, SCAN_BLK>>>(n_rows);
    scan3<<<nb_nodes, 256>>>(n_rows, nb_scan);
    reorder_kernel<<<nb_edges, 256>>>(src, dst, n_edges);

    gather_self_kernel<<<nb_self + nb_gath, 256, SELF_SMEM>>>(
        x, Ws, out, n_rows, nb_self);

    final_kernel<<<nb_self, 256, FINAL_SMEM>>>(Wn, b, out, n_rows);
}